// round 10
// baseline (speedup 1.0000x reference)
#include <cuda_runtime.h>
#include <cuda_fp16.h>
#include <cstdint>
#include <math.h>

#define DM     1024
#define BATCHN 1024
#define HEADS  16
#define DK     64
#define NCHUNK 4
#define CB     (BATCHN / NCHUNK)        // 256 batches per chunk

// ---------------- scratch (no allocation allowed) ----------------
__device__ float g_qkv[3u * BATCHN * DM];            // q | k | v fp32
__device__ float g_beta[BATCHN * HEADS];
__device__ __half g_xh[BATCHN * DM];                 // x split hi (fp16)
__device__ __half g_xl[BATCHN * DM];                 // x split lo (fp16)
__device__ __half g_wt[4u * DM * DM];                // W^T fp16: Wq,Wk,Wv,Wo
__device__ __half g_ohh[BATCHN * DM];                // outh split hi
__device__ __half g_ohl[BATCHN * DM];                // outh split lo

__device__ __forceinline__ void cp16(uint32_t s, const void* g) {
    asm volatile("cp.async.cg.shared.global [%0], [%1], 16;" :: "r"(s), "l"(g));
}

// ---------------------------------------------------------------------------
// split fp32 -> fp16 hi/lo
// ---------------------------------------------------------------------------
__global__ __launch_bounds__(256) void split_kernel(
    const float* __restrict__ in, __half* __restrict__ hi, __half* __restrict__ lo)
{
    int idx = blockIdx.x * 256 + threadIdx.x;   // float4 index
    float4 v = reinterpret_cast<const float4*>(in)[idx];
    float f[4] = {v.x, v.y, v.z, v.w};
    __half h[4], l[4];
#pragma unroll
    for (int i = 0; i < 4; i++) {
        h[i] = __float2half_rn(f[i]);
        l[i] = __float2half_rn(f[i] - __half2float(h[i]));
    }
    __half2* h2 = reinterpret_cast<__half2*>(hi);
    __half2* l2 = reinterpret_cast<__half2*>(lo);
    h2[idx * 2 + 0] = __half2(h[0], h[1]);
    h2[idx * 2 + 1] = __half2(h[2], h[3]);
    l2[idx * 2 + 0] = __half2(l[0], l[1]);
    l2[idx * 2 + 1] = __half2(l[2], l[3]);
}

// ---------------------------------------------------------------------------
// transpose + fp16: W[K][N] -> Wt[N][K] fp16. z selects matrix.
// ---------------------------------------------------------------------------
__global__ __launch_bounds__(256) void transhalf_kernel(
    const float* __restrict__ W0, const float* __restrict__ W1,
    const float* __restrict__ W2, const float* __restrict__ W3,
    __half* __restrict__ H)
{
    __shared__ float tile[32][33];
    const int z = blockIdx.z;
    const float* W = (z == 0) ? W0 : (z == 1) ? W1 : (z == 2) ? W2 : W3;
    __half* Ht = H + (size_t)z * DM * DM;
    const int tx = threadIdx.x & 31, ty = threadIdx.x >> 5;
    const int nb = blockIdx.x * 32, kb = blockIdx.y * 32;
#pragma unroll
    for (int i = 0; i < 4; i++) {
        int k = kb + ty + i * 8;
        tile[ty + i * 8][tx] = W[(size_t)k * DM + nb + tx];
    }
    __syncthreads();
#pragma unroll
    for (int i = 0; i < 4; i++) {
        int n = nb + ty + i * 8;
        Ht[(size_t)n * DM + kb + tx] = __float2half_rn(tile[tx][ty + i * 8]);
    }
}

// ---------------------------------------------------------------------------
// fp16 2-pass GEMM on mma.sync: C = Ah*Bh + Al*Bh  (A split, B plain fp16).
// CTA tile 64x128, BK=32, 8 warps (2x4), warp tile 32x32.
// 4-stage cp.async pipeline, XOR-swizzled 64B rows, one barrier / iteration.
// ---------------------------------------------------------------------------
#define OFF_AH    0
#define OFF_AL    4096
#define OFF_BH    8192
#define MM_STAGE  16384                 // Ah(4K) | Al(4K) | Bh(8K)
#define MM_SMEM   (4 * MM_STAGE)        // 65536

__device__ __forceinline__ void mma_f16(float* c, const uint32_t* a, const uint32_t* b) {
    asm volatile(
        "mma.sync.aligned.m16n8k16.row.col.f32.f16.f16.f32 "
        "{%0,%1,%2,%3}, {%4,%5,%6,%7}, {%8,%9}, {%0,%1,%2,%3};"
        : "+f"(c[0]), "+f"(c[1]), "+f"(c[2]), "+f"(c[3])
        : "r"(a[0]), "r"(a[1]), "r"(a[2]), "r"(a[3]), "r"(b[0]), "r"(b[1]));
}

// One stage: Ah/Al 64 rows x 64B, Bh 128 rows x 64B. XOR swizzle c^=(r>>1)&3.
__device__ __forceinline__ void cp_stage(
    uint32_t smStage, const char* aH, const char* aL, const char* bH,
    int ktBytes, int tid)
{
    {   // A: thread t -> row t>>2, chunk t&3
        const int r = tid >> 2, c = tid & 3;
        const int sw = (r >> 1) & 3;
        const size_t goff = ((size_t)r << 11) + (size_t)ktBytes + (c << 4);
        const uint32_t soff = r * 64 + ((c ^ sw) << 4);
        cp16(smStage + OFF_AH + soff, aH + goff);
        cp16(smStage + OFF_AL + soff, aL + goff);
    }
    {   // B: thread t -> row t>>1, chunks (t&1)*2, +1
        const int r = tid >> 1;
        const int sw = (r >> 1) & 3;
#pragma unroll
        for (int cc = 0; cc < 2; cc++) {
            const int c = (tid & 1) * 2 + cc;
            const size_t goff = ((size_t)r << 11) + (size_t)ktBytes + (c << 4);
            const uint32_t soff = r * 64 + ((c ^ sw) << 4);
            cp16(smStage + OFF_BH + soff, bH + goff);
        }
    }
    asm volatile("cp.async.commit_group;");
}

__global__ __launch_bounds__(256, 3) void mm_kernel(
    const __half* __restrict__ Ah, const __half* __restrict__ Al,
    const __half* __restrict__ Bt0, const __half* __restrict__ Bt1,
    const __half* __restrict__ Bt2,
    float* __restrict__ C0, float* __restrict__ C1, float* __restrict__ C2,
    const float* __restrict__ bias)
{
    extern __shared__ char sm[];
    uint32_t smbase;
    asm("{ .reg .u64 t; cvta.to.shared.u64 t, %1; cvt.u32.u64 %0, t; }"
        : "=r"(smbase) : "l"(sm));

    const int tid = threadIdx.x;
    const int warp = tid >> 5, lane = tid & 31;
    const int g = lane >> 2, tg = lane & 3;
    const int z = blockIdx.z;
    const __half* Bt = (z == 0) ? Bt0 : (z == 1) ? Bt1 : Bt2;
    float* C = (z == 0) ? C0 : (z == 1) ? C1 : C2;

    const int rowBase = blockIdx.y * 64;
    const int colBase = blockIdx.x * 128;
    const int warpRow = (warp & 1) * 32;       // 2 warp-rows of 32
    const int warpCol = (warp >> 1) * 32;      // 4 warp-cols of 32

    const char* aHp = (const char*)Ah + ((size_t)rowBase << 11);
    const char* aLp = (const char*)Al + ((size_t)rowBase << 11);
    const char* bHp = (const char*)Bt + ((size_t)colBase << 11);

    const uint32_t sig = (uint32_t)(g & 6) << 3;
    const uint32_t kp[2][2] = { { (0u ^ sig),  (16u ^ sig) },
                                { (32u ^ sig), (48u ^ sig) } };
    uint32_t aBase[2], bBase[4];
#pragma unroll
    for (int mi = 0; mi < 2; mi++)
        aBase[mi] = (uint32_t)((warpRow + mi * 16 + g) * 64 + tg * 4);
#pragma unroll
    for (int ni = 0; ni < 4; ni++)
        bBase[ni] = (uint32_t)(OFF_BH + (warpCol + ni * 8 + g) * 64 + tg * 4);

    float acc[2][4][4];
#pragma unroll
    for (int mi = 0; mi < 2; mi++)
#pragma unroll
        for (int ni = 0; ni < 4; ni++)
#pragma unroll
            for (int e = 0; e < 4; e++) acc[mi][ni][e] = 0.f;

    cp_stage(smbase + 0 * MM_STAGE, aHp, aLp, bHp, 0,   tid);
    cp_stage(smbase + 1 * MM_STAGE, aHp, aLp, bHp, 64,  tid);
    cp_stage(smbase + 2 * MM_STAGE, aHp, aLp, bHp, 128, tid);

    for (int it = 0; it < 32; it++) {
        if (it < 30)       asm volatile("cp.async.wait_group 2;" ::: "memory");
        else if (it == 30) asm volatile("cp.async.wait_group 1;" ::: "memory");
        else               asm volatile("cp.async.wait_group 0;" ::: "memory");
        __syncthreads();
        if (it + 3 < 32)
            cp_stage(smbase + ((it + 3) & 3) * MM_STAGE, aHp, aLp, bHp,
                     (it + 3) * 64, tid);
        const uint32_t so = smbase + (it & 3) * MM_STAGE;

#pragma unroll
        for (int ks = 0; ks < 2; ks++) {
            const uint32_t k0 = kp[ks][0], k1 = kp[ks][1];
            uint32_t ahf[2][4];
#pragma unroll
            for (int mi = 0; mi < 2; mi++) {
                const uint32_t p0 = so + aBase[mi];
                ahf[mi][0] = *(const uint32_t*)__cvta_shared_to_generic(p0 + k0);
                ahf[mi][1] = *(const uint32_t*)__cvta_shared_to_generic(p0 + k0 + 512);
                ahf[mi][2] = *(const uint32_t*)__cvta_shared_to_generic(p0 + k1);
                ahf[mi][3] = *(const uint32_t*)__cvta_shared_to_generic(p0 + k1 + 512);
            }
            uint32_t bhf[4][2];
#pragma unroll
            for (int ni = 0; ni < 4; ni++) {
                const uint32_t p0 = so + bBase[ni];
                bhf[ni][0] = *(const uint32_t*)__cvta_shared_to_generic(p0 + k0);
                bhf[ni][1] = *(const uint32_t*)__cvta_shared_to_generic(p0 + k1);
            }
#pragma unroll
            for (int mi = 0; mi < 2; mi++)
#pragma unroll
                for (int ni = 0; ni < 4; ni++)
                    mma_f16(acc[mi][ni], ahf[mi], bhf[ni]);
            {
                uint32_t alf[2][4];
#pragma unroll
                for (int mi = 0; mi < 2; mi++) {
                    const uint32_t p0 = so + aBase[mi] + (OFF_AL - OFF_AH);
                    alf[mi][0] = *(const uint32_t*)__cvta_shared_to_generic(p0 + k0);
                    alf[mi][1] = *(const uint32_t*)__cvta_shared_to_generic(p0 + k0 + 512);
                    alf[mi][2] = *(const uint32_t*)__cvta_shared_to_generic(p0 + k1);
                    alf[mi][3] = *(const uint32_t*)__cvta_shared_to_generic(p0 + k1 + 512);
                }
#pragma unroll
                for (int mi = 0; mi < 2; mi++)
#pragma unroll
                    for (int ni = 0; ni < 4; ni++)
                        mma_f16(acc[mi][ni], alf[mi], bhf[ni]);
            }
        }
    }

    // epilogue
#pragma unroll
    for (int mi = 0; mi < 2; mi++) {
        const int row0 = rowBase + warpRow + mi * 16 + g;
#pragma unroll
        for (int ni = 0; ni < 4; ni++) {
            const int col = colBase + warpCol + ni * 8 + tg * 2;
            float b0 = 0.f, b1 = 0.f;
            if (bias) { b0 = bias[col]; b1 = bias[col + 1]; }
            float2 v0 = make_float2(acc[mi][ni][0] + b0, acc[mi][ni][1] + b1);
            float2 v1 = make_float2(acc[mi][ni][2] + b0, acc[mi][ni][3] + b1);
            *reinterpret_cast<float2*>(&C[(size_t)row0 * DM + col]) = v0;
            *reinterpret_cast<float2*>(&C[(size_t)(row0 + 8) * DM + col]) = v1;
        }
    }
}

// ---------------------------------------------------------------------------
// beta = sigmoid(x @ Wg)
// ---------------------------------------------------------------------------
__global__ __launch_bounds__(512) void beta_kernel(
    const float* __restrict__ x, const float* __restrict__ Wg,
    float* __restrict__ beta)
{
    __shared__ float xs[DM];
    const int b = blockIdx.x;
    for (int i = threadIdx.x; i < DM; i += 512) xs[i] = x[(size_t)b * DM + i];
    __syncthreads();
    const int w = threadIdx.x >> 5, lane = threadIdx.x & 31;
    float s = 0.f;
    for (int j = lane; j < DM; j += 32) s = fmaf(xs[j], Wg[(size_t)j * HEADS + w], s);
#pragma unroll
    for (int off = 16; off; off >>= 1) s += __shfl_xor_sync(0xffffffffu, s, off);
    if (lane == 0) beta[b * HEADS + w] = 1.f / (1.f + expf(-s));
}

// ---------------------------------------------------------------------------
// fast-weight delta rule, one 64-thread CTA per (b,h). All pointers are
// pre-offset per chunk by the host. Streaming stores via __stcs.
// ---------------------------------------------------------------------------
__global__ __launch_bounds__(64) void fastweight_kernel(
    const float* __restrict__ weights,
    const float* __restrict__ q, const float* __restrict__ k,
    const float* __restrict__ v, const float* __restrict__ beta,
    float* __restrict__ nw,
    __half* __restrict__ ohh, __half* __restrict__ ohl)
{
    __shared__ float Wsh[DK * DK];          // unpadded 16KB
    __shared__ float ksh[DK], qsh[DK], dsh[DK];

    const int bh = blockIdx.x;
    const int t  = threadIdx.x;

    uint32_t sW;
    asm("{ .reg .u64 a; cvta.to.shared.u64 a, %1; cvt.u32.u64 %0, a; }"
        : "=r"(sW) : "l"(Wsh));
    const char* Wp = (const char*)(weights + (size_t)bh * (DK * DK));
#pragma unroll
    for (int i = 0; i < 16; i++) {
        const uint32_t off = (uint32_t)(i * 64 + t) * 16;   // 16B chunks
        cp16(sW + off, Wp + off);
    }
    asm volatile("cp.async.commit_group;");

    const size_t base = (size_t)(bh >> 4) * DM + (size_t)(bh & 15) * DK + t;
    const float kval  = k[base];
    const float qval  = q[base];
    const float vval  = v[base];
    const float betav = beta[bh];
    ksh[t] = kval;
    qsh[t] = qval;

    asm volatile("cp.async.wait_group 0;" ::: "memory");
    __syncthreads();

    float s = 0.f;
#pragma unroll
    for (int j = 0; j < DK; j++) {
        const int c = (j + t) & 63;
        s = fmaf(Wsh[t * DK + c], ksh[c], s);
    }
    const float dv = betav * (vval - s);
    dsh[t] = dv;
    __syncthreads();

    float s2 = 0.f, kq = 0.f;
#pragma unroll
    for (int j = 0; j < DK; j++) {
        const int c = (j + t) & 63;
        s2 = fmaf(Wsh[t * DK + c], qsh[c], s2);
        kq = fmaf(ksh[c], qsh[c], kq);
    }
    const float o = s2 + dv * kq;
    const __half oh = __float2half_rn(o);
    ohh[base] = oh;
    ohl[base] = __float2half_rn(o - __half2float(oh));

    float* NW = nw + (size_t)bh * (DK * DK);
    const int r0 = t >> 4, c4 = (t & 15) << 2;
    float4 k4;
    k4.x = ksh[c4 + 0]; k4.y = ksh[c4 + 1]; k4.z = ksh[c4 + 2]; k4.w = ksh[c4 + 3];
#pragma unroll
    for (int i = 0; i < 16; i++) {
        const int row = r0 + i * 4;
        const float d = dsh[row];
        const float4 w4 = *reinterpret_cast<const float4*>(&Wsh[row * DK + c4]);
        float4 o4;
        o4.x = w4.x + d * k4.x;
        o4.y = w4.y + d * k4.y;
        o4.z = w4.z + d * k4.z;
        o4.w = w4.w + d * k4.w;
        __stcs(reinterpret_cast<float4*>(&NW[row * DK + c4]), o4);
    }
}

// ---------------------------------------------------------------------------
extern "C" void kernel_launch(void* const* d_in, const int* in_sizes, int n_in,
                              void* d_out, int out_size)
{
    const float* x       = (const float*)d_in[0];
    const float* weights = (const float*)d_in[1];
    const float* Wq      = (const float*)d_in[2];
    const float* Wk      = (const float*)d_in[3];
    const float* Wv      = (const float*)d_in[4];
    const float* Wg      = (const float*)d_in[5];
    const float* Wo      = (const float*)d_in[6];
    const float* bo      = (const float*)d_in[7];

    float* out = (float*)d_out;
    float* nw  = out + (size_t)BATCHN * DM;

    float *qb, *bb;
    __half *xh, *xl, *wt, *ohh, *ohl;
    cudaGetSymbolAddress((void**)&qb,  g_qkv);
    cudaGetSymbolAddress((void**)&bb,  g_beta);
    cudaGetSymbolAddress((void**)&xh,  g_xh);
    cudaGetSymbolAddress((void**)&xl,  g_xl);
    cudaGetSymbolAddress((void**)&wt,  g_wt);
    cudaGetSymbolAddress((void**)&ohh, g_ohh);
    cudaGetSymbolAddress((void**)&ohl, g_ohl);
    float* kb = qb + (size_t)BATCHN * DM;
    float* vb = kb + (size_t)BATCHN * DM;

    cudaFuncSetAttribute(mm_kernel, cudaFuncAttributeMaxDynamicSharedMemorySize, MM_SMEM);

    const size_t MS = (size_t)DM * DM;
    const cudaStream_t s0 = 0;
    const cudaStream_t s1 = cudaStreamPerThread;

    // fork/join events (created fresh each call; deterministic sequence)
    cudaEvent_t eQ[NCHUNK], eF[NCHUNK];
    for (int c = 0; c < NCHUNK; c++) {
        cudaEventCreateWithFlags(&eQ[c], cudaEventDisableTiming);
        cudaEventCreateWithFlags(&eF[c], cudaEventDisableTiming);
    }

    // --- prep on s0 ---
    transhalf_kernel<<<dim3(32, 32, 4), 256, 0, s0>>>(Wq, Wk, Wv, Wo, wt);
    split_kernel<<<1024, 256, 0, s0>>>(x, xh, xl);
    beta_kernel<<<BATCHN, 512, 0, s0>>>(x, Wg, bb);

    // --- QKV chunks on s0 ---
    for (int c = 0; c < NCHUNK; c++) {
        const size_t ro = (size_t)c * CB * DM;         // row offset (elements)
        mm_kernel<<<dim3(8, CB / 64, 3), 256, MM_SMEM, s0>>>(
            xh + ro, xl + ro,
            wt + 0 * MS, wt + 1 * MS, wt + 2 * MS,
            qb + ro, kb + ro, vb + ro, nullptr);
        cudaEventRecord(eQ[c], s0);
    }

    // --- fastweight chunks on s1 (each waits its QKV chunk) ---
    for (int c = 0; c < NCHUNK; c++) {
        const size_t ro = (size_t)c * CB * DM;
        const size_t wo = (size_t)c * CB * HEADS * DK * DK;
        const size_t bo_ = (size_t)c * CB * HEADS;
        cudaStreamWaitEvent(s1, eQ[c], 0);
        fastweight_kernel<<<CB * HEADS, 64, 0, s1>>>(
            weights + wo, qb + ro, kb + ro, vb + ro, bb + bo_,
            nw + wo, ohh + ro, ohl + ro);
        cudaEventRecord(eF[c], s1);
    }

    // --- Wo chunks on s0 (each waits its fastweight chunk; joins s1) ---
    for (int c = 0; c < NCHUNK; c++) {
        const size_t ro = (size_t)c * CB * DM;
        cudaStreamWaitEvent(s0, eF[c], 0);
        mm_kernel<<<dim3(8, CB / 64, 1), 256, MM_SMEM, s0>>>(
            ohh + ro, ohl + ro,
            wt + 3 * MS, wt + 3 * MS, wt + 3 * MS,
            out + ro, out + ro, out + ro, bo);
    }
}

// round 11
// speedup vs baseline: 1.6624x; 1.6624x over previous
#include <cuda_runtime.h>
#include <cuda_fp16.h>
#include <cstdint>
#include <math.h>

#define DM     1024
#define BATCHN 1024
#define HEADS  16
#define DK     64

// ---------------- scratch (no allocation allowed) ----------------
__device__ float g_qkv[3u * BATCHN * DM];            // q | k | v fp32
__device__ float g_beta[BATCHN * HEADS];
__device__ __half g_xh[BATCHN * DM];                 // x split hi (fp16)
__device__ __half g_xl[BATCHN * DM];                 // x split lo (fp16)
__device__ __half g_wt[4u * DM * DM];                // W^T fp16: Wq,Wk,Wv,Wo
__device__ __half g_ohh[BATCHN * DM];                // outh split hi
__device__ __half g_ohl[BATCHN * DM];                // outh split lo

__device__ __forceinline__ uint32_t smaddr(const void* p) {
    uint32_t a;
    asm("{ .reg .u64 t; cvta.to.shared.u64 t, %1; cvt.u32.u64 %0, t; }" : "=r"(a) : "l"(p));
    return a;
}
__device__ __forceinline__ void cp16(uint32_t s, const void* g) {
    asm volatile("cp.async.cg.shared.global [%0], [%1], 16;" :: "r"(s), "l"(g));
}
__device__ __forceinline__ void cp4(uint32_t s, const void* g) {
    asm volatile("cp.async.ca.shared.global [%0], [%1], 4;" :: "r"(s), "l"(g));
}

// ---------------------------------------------------------------------------
// fused: split x -> fp16 hi/lo  AND  beta = sigmoid(x @ Wg). One CTA/batch.
// ---------------------------------------------------------------------------
__global__ __launch_bounds__(256) void splitbeta_kernel(
    const float* __restrict__ x, __half* __restrict__ hi, __half* __restrict__ lo,
    const float* __restrict__ Wg, float* __restrict__ beta)
{
    __shared__ float xs[DM];
    const int b = blockIdx.x, t = threadIdx.x;
    const int idx = b * 256 + t;
    float4 v = reinterpret_cast<const float4*>(x)[idx];
    float f[4] = {v.x, v.y, v.z, v.w};
    __half h[4], l[4];
#pragma unroll
    for (int i = 0; i < 4; i++) {
        h[i] = __float2half_rn(f[i]);
        l[i] = __float2half_rn(f[i] - __half2float(h[i]));
        xs[t * 4 + i] = f[i];
    }
    __half2* h2 = reinterpret_cast<__half2*>(hi);
    __half2* l2 = reinterpret_cast<__half2*>(lo);
    h2[idx * 2 + 0] = __half2(h[0], h[1]);
    h2[idx * 2 + 1] = __half2(h[2], h[3]);
    l2[idx * 2 + 0] = __half2(l[0], l[1]);
    l2[idx * 2 + 1] = __half2(l[2], l[3]);
    __syncthreads();

    const int w = t >> 5, lane = t & 31;
    const int hh = w * 2 + (lane >> 4);        // head for this half-warp
    const int lj = lane & 15;
    float s = 0.f;
#pragma unroll 8
    for (int i = 0; i < 64; i++) {
        const int j = lj + (i << 4);
        s = fmaf(xs[j], Wg[j * HEADS + hh], s);
    }
#pragma unroll
    for (int off = 8; off; off >>= 1) s += __shfl_xor_sync(0xffffffffu, s, off);
    if (lj == 0) beta[b * HEADS + hh] = 1.f / (1.f + expf(-s));
}

// ---------------------------------------------------------------------------
// transpose + fp16: W[K][N] -> Wt[N][K] fp16. z selects matrix.
// ---------------------------------------------------------------------------
__global__ __launch_bounds__(256) void transhalf_kernel(
    const float* __restrict__ W0, const float* __restrict__ W1,
    const float* __restrict__ W2, const float* __restrict__ W3,
    __half* __restrict__ H)
{
    __shared__ float tile[32][33];
    const int z = blockIdx.z;
    const float* W = (z == 0) ? W0 : (z == 1) ? W1 : (z == 2) ? W2 : W3;
    __half* Ht = H + (size_t)z * DM * DM;
    const int tx = threadIdx.x & 31, ty = threadIdx.x >> 5;
    const int nb = blockIdx.x * 32, kb = blockIdx.y * 32;
#pragma unroll
    for (int i = 0; i < 4; i++) {
        int k = kb + ty + i * 8;
        tile[ty + i * 8][tx] = W[(size_t)k * DM + nb + tx];
    }
    __syncthreads();
#pragma unroll
    for (int i = 0; i < 4; i++) {
        int n = nb + ty + i * 8;
        Ht[(size_t)n * DM + kb + tx] = __float2half_rn(tile[tx][ty + i * 8]);
    }
}

// ---------------------------------------------------------------------------
// fp16 2-pass GEMM on mma.sync: C = Ah*Bh + Al*Bh.
// CTA tile 64xBN (BN=128 or 64), BK=32, 8 warps, 4-stage cp.async pipeline.
// ---------------------------------------------------------------------------
#define OFF_AH    0
#define OFF_AL    4096
#define OFF_BH    8192

__device__ __forceinline__ void mma_f16(float* c, const uint32_t* a, const uint32_t* b) {
    asm volatile(
        "mma.sync.aligned.m16n8k16.row.col.f32.f16.f16.f32 "
        "{%0,%1,%2,%3}, {%4,%5,%6,%7}, {%8,%9}, {%0,%1,%2,%3};"
        : "+f"(c[0]), "+f"(c[1]), "+f"(c[2]), "+f"(c[3])
        : "r"(a[0]), "r"(a[1]), "r"(a[2]), "r"(a[3]), "r"(b[0]), "r"(b[1]));
}

template<int BN>
__device__ __forceinline__ void cp_stage_t(
    uint32_t smStage, const char* aH, const char* aL, const char* bH,
    int ktBytes, int tid)
{
    {   // A: 64 rows x 64B; thread t -> row t>>2, chunk t&3
        const int r = tid >> 2, c = tid & 3;
        const int sw = (r >> 1) & 3;
        const size_t goff = ((size_t)r << 11) + (size_t)ktBytes + (c << 4);
        const uint32_t soff = r * 64 + ((c ^ sw) << 4);
        cp16(smStage + OFF_AH + soff, aH + goff);
        cp16(smStage + OFF_AL + soff, aL + goff);
    }
    if (BN == 128) {   // B: 128 rows; thread t -> row t>>1, chunks (t&1)*2,+1
        const int r = tid >> 1;
        const int sw = (r >> 1) & 3;
#pragma unroll
        for (int cc = 0; cc < 2; cc++) {
            const int c = (tid & 1) * 2 + cc;
            const size_t goff = ((size_t)r << 11) + (size_t)ktBytes + (c << 4);
            const uint32_t soff = r * 64 + ((c ^ sw) << 4);
            cp16(smStage + OFF_BH + soff, bH + goff);
        }
    } else {           // B: 64 rows; thread t -> row t>>2, chunk t&3
        const int r = tid >> 2, c = tid & 3;
        const int sw = (r >> 1) & 3;
        const size_t goff = ((size_t)r << 11) + (size_t)ktBytes + (c << 4);
        const uint32_t soff = r * 64 + ((c ^ sw) << 4);
        cp16(smStage + OFF_BH + soff, bH + goff);
    }
    asm volatile("cp.async.commit_group;");
}

template<int BN, int MINB>
__global__ __launch_bounds__(256, MINB) void mm_kernel(
    const __half* __restrict__ Ah, const __half* __restrict__ Al,
    const __half* __restrict__ Bt0, const __half* __restrict__ Bt1,
    const __half* __restrict__ Bt2,
    float* __restrict__ C0, float* __restrict__ C1, float* __restrict__ C2,
    const float* __restrict__ bias)
{
    constexpr int STAGE = 8192 + BN * 64;
    constexpr int NI = BN / 32;
    extern __shared__ char sm[];
    uint32_t smbase;
    asm("{ .reg .u64 t; cvta.to.shared.u64 t, %1; cvt.u32.u64 %0, t; }"
        : "=r"(smbase) : "l"(sm));

    const int tid = threadIdx.x;
    const int warp = tid >> 5, lane = tid & 31;
    const int g = lane >> 2, tg = lane & 3;
    const int z = blockIdx.z;
    const __half* Bt = (z == 0) ? Bt0 : (z == 1) ? Bt1 : Bt2;
    float* C = (z == 0) ? C0 : (z == 1) ? C1 : C2;

    const int rowBase = blockIdx.y * 64;
    const int colBase = blockIdx.x * BN;
    const int warpRow = (warp & 1) * 32;
    const int warpCol = (warp >> 1) * (BN / 4);

    const char* aHp = (const char*)Ah + ((size_t)rowBase << 11);
    const char* aLp = (const char*)Al + ((size_t)rowBase << 11);
    const char* bHp = (const char*)Bt + ((size_t)colBase << 11);

    const uint32_t sig = (uint32_t)(g & 6) << 3;
    const uint32_t kp[2][2] = { { (0u ^ sig),  (16u ^ sig) },
                                { (32u ^ sig), (48u ^ sig) } };
    uint32_t aBase[2], bBase[NI];
#pragma unroll
    for (int mi = 0; mi < 2; mi++)
        aBase[mi] = (uint32_t)((warpRow + mi * 16 + g) * 64 + tg * 4);
#pragma unroll
    for (int ni = 0; ni < NI; ni++)
        bBase[ni] = (uint32_t)(OFF_BH + (warpCol + ni * 8 + g) * 64 + tg * 4);

    float acc[2][NI][4];
#pragma unroll
    for (int mi = 0; mi < 2; mi++)
#pragma unroll
        for (int ni = 0; ni < NI; ni++)
#pragma unroll
            for (int e = 0; e < 4; e++) acc[mi][ni][e] = 0.f;

    cp_stage_t<BN>(smbase + 0 * STAGE, aHp, aLp, bHp, 0,   tid);
    cp_stage_t<BN>(smbase + 1 * STAGE, aHp, aLp, bHp, 64,  tid);
    cp_stage_t<BN>(smbase + 2 * STAGE, aHp, aLp, bHp, 128, tid);

    for (int it = 0; it < 32; it++) {
        if (it < 30)       asm volatile("cp.async.wait_group 2;" ::: "memory");
        else if (it == 30) asm volatile("cp.async.wait_group 1;" ::: "memory");
        else               asm volatile("cp.async.wait_group 0;" ::: "memory");
        __syncthreads();
        if (it + 3 < 32)
            cp_stage_t<BN>(smbase + ((it + 3) & 3) * STAGE, aHp, aLp, bHp,
                           (it + 3) * 64, tid);
        const uint32_t so = smbase + (it & 3) * STAGE;

#pragma unroll
        for (int ks = 0; ks < 2; ks++) {
            const uint32_t k0 = kp[ks][0], k1 = kp[ks][1];
            uint32_t ahf[2][4];
#pragma unroll
            for (int mi = 0; mi < 2; mi++) {
                const uint32_t p0 = so + aBase[mi];
                ahf[mi][0] = *(const uint32_t*)__cvta_shared_to_generic(p0 + k0);
                ahf[mi][1] = *(const uint32_t*)__cvta_shared_to_generic(p0 + k0 + 512);
                ahf[mi][2] = *(const uint32_t*)__cvta_shared_to_generic(p0 + k1);
                ahf[mi][3] = *(const uint32_t*)__cvta_shared_to_generic(p0 + k1 + 512);
            }
            uint32_t bhf[NI][2];
#pragma unroll
            for (int ni = 0; ni < NI; ni++) {
                const uint32_t p0 = so + bBase[ni];
                bhf[ni][0] = *(const uint32_t*)__cvta_shared_to_generic(p0 + k0);
                bhf[ni][1] = *(const uint32_t*)__cvta_shared_to_generic(p0 + k1);
            }
#pragma unroll
            for (int mi = 0; mi < 2; mi++)
#pragma unroll
                for (int ni = 0; ni < NI; ni++)
                    mma_f16(acc[mi][ni], ahf[mi], bhf[ni]);
            {
                uint32_t alf[2][4];
#pragma unroll
                for (int mi = 0; mi < 2; mi++) {
                    const uint32_t p0 = so + aBase[mi] + (OFF_AL - OFF_AH);
                    alf[mi][0] = *(const uint32_t*)__cvta_shared_to_generic(p0 + k0);
                    alf[mi][1] = *(const uint32_t*)__cvta_shared_to_generic(p0 + k0 + 512);
                    alf[mi][2] = *(const uint32_t*)__cvta_shared_to_generic(p0 + k1);
                    alf[mi][3] = *(const uint32_t*)__cvta_shared_to_generic(p0 + k1 + 512);
                }
#pragma unroll
                for (int mi = 0; mi < 2; mi++)
#pragma unroll
                    for (int ni = 0; ni < NI; ni++)
                        mma_f16(acc[mi][ni], alf[mi], bhf[ni]);
            }
        }
    }

    // epilogue
#pragma unroll
    for (int mi = 0; mi < 2; mi++) {
        const int row0 = rowBase + warpRow + mi * 16 + g;
#pragma unroll
        for (int ni = 0; ni < NI; ni++) {
            const int col = colBase + warpCol + ni * 8 + tg * 2;
            float b0 = 0.f, b1 = 0.f;
            if (bias) { b0 = bias[col]; b1 = bias[col + 1]; }
            float2 v0 = make_float2(acc[mi][ni][0] + b0, acc[mi][ni][1] + b1);
            float2 v1 = make_float2(acc[mi][ni][2] + b0, acc[mi][ni][3] + b1);
            *reinterpret_cast<float2*>(&C[(size_t)row0 * DM + col]) = v0;
            *reinterpret_cast<float2*>(&C[(size_t)(row0 + 8) * DM + col]) = v1;
        }
    }
}

#define MM_SMEM_128 (4 * (8192 + 128 * 64))   // 65536
#define MM_SMEM_64  (4 * (8192 + 64 * 64))    // 49152

// ---------------------------------------------------------------------------
// persistent double-buffered fast-weight kernel. One 64-thread CTA handles
// FW_ITERS consecutive (b,h); W,k,q,v,beta for step i+1 prefetched via
// cp.async while step i computes/stores.
// ---------------------------------------------------------------------------
#define FW_ITERS 8

__global__ __launch_bounds__(64) void fastweight_kernel(
    const float* __restrict__ weights,
    const float* __restrict__ q, const float* __restrict__ k,
    const float* __restrict__ v, const float* __restrict__ beta,
    float* __restrict__ nw,
    __half* __restrict__ ohh, __half* __restrict__ ohl)
{
    __shared__ __align__(16) float Wbuf[2][DK * DK];      // 2 x 16KB
    __shared__ __align__(16) float kqv[2][3][DK];         // k | q | v
    __shared__ float betasm[2];
    __shared__ float dsh[DK];

    const int t   = threadIdx.x;
    const int bh0 = blockIdx.x * FW_ITERS;

    // ---- prefetch helper (inlined twice) ----
#define FW_PREFETCH(slot, bh)                                                   \
    do {                                                                        \
        const uint32_t sW = smaddr(&Wbuf[slot][0]);                             \
        const char* Wp = (const char*)(weights + (size_t)(bh) * (DK * DK));     \
        _Pragma("unroll")                                                       \
        for (int i = 0; i < 16; i++) {                                          \
            const uint32_t off = (uint32_t)(i * 64 + t) * 16;                   \
            cp16(sW + off, Wp + off);                                           \
        }                                                                       \
        const size_t gb = (size_t)((bh) >> 4) * DM + (size_t)((bh) & 15) * DK;  \
        if (t < 16)      cp16(smaddr(&kqv[slot][0][0]) + t * 16,                \
                              (const char*)(k + gb) + t * 16);                  \
        else if (t < 32) cp16(smaddr(&kqv[slot][1][0]) + (t - 16) * 16,         \
                              (const char*)(q + gb) + (t - 16) * 16);           \
        else if (t < 48) cp16(smaddr(&kqv[slot][2][0]) + (t - 32) * 16,         \
                              (const char*)(v + gb) + (t - 32) * 16);           \
        else if (t == 48) cp4(smaddr(&betasm[slot]), beta + (bh));              \
        asm volatile("cp.async.commit_group;");                                 \
    } while (0)

    FW_PREFETCH(0, bh0);

    for (int i = 0; i < FW_ITERS; i++) {
        const int slot = i & 1;
        if (i + 1 < FW_ITERS) {
            FW_PREFETCH((i + 1) & 1, bh0 + i + 1);
            asm volatile("cp.async.wait_group 1;" ::: "memory");
        } else {
            asm volatile("cp.async.wait_group 0;" ::: "memory");
        }
        __syncthreads();

        const int bh = bh0 + i;
        const float* Wsh = Wbuf[slot];
        const float* ksh = kqv[slot][0];
        const float* qsh = kqv[slot][1];
        const float  vval  = kqv[slot][2][t];
        const float  betav = betasm[slot];
        const size_t gb = (size_t)(bh >> 4) * DM + (size_t)(bh & 15) * DK + t;

        // v_existing: row t . k (diagonal, conflict-free)
        float s = 0.f;
#pragma unroll
        for (int j = 0; j < DK; j++) {
            const int c = (j + t) & 63;
            s = fmaf(Wsh[t * DK + c], ksh[c], s);
        }
        const float dv = betav * (vval - s);
        dsh[t] = dv;
        __syncthreads();

        float s2 = 0.f, kq = 0.f;
#pragma unroll
        for (int j = 0; j < DK; j++) {
            const int c = (j + t) & 63;
            s2 = fmaf(Wsh[t * DK + c], qsh[c], s2);
            kq = fmaf(ksh[c], qsh[c], kq);
        }
        const float o = s2 + dv * kq;
        const __half oh = __float2half_rn(o);
        ohh[gb] = oh;
        ohl[gb] = __float2half_rn(o - __half2float(oh));

        float* NW = nw + (size_t)bh * (DK * DK);
        const int r0 = t >> 4, c4 = (t & 15) << 2;
        float4 k4;
        k4.x = ksh[c4 + 0]; k4.y = ksh[c4 + 1]; k4.z = ksh[c4 + 2]; k4.w = ksh[c4 + 3];
#pragma unroll
        for (int j = 0; j < 16; j++) {
            const int row = r0 + j * 4;
            const float d = dsh[row];
            const float4 w4 = *reinterpret_cast<const float4*>(&Wsh[row * DK + c4]);
            float4 o4;
            o4.x = w4.x + d * k4.x;
            o4.y = w4.y + d * k4.y;
            o4.z = w4.z + d * k4.z;
            o4.w = w4.w + d * k4.w;
            __stcs(reinterpret_cast<float4*>(&NW[row * DK + c4]), o4);
        }
        __syncthreads();
    }
#undef FW_PREFETCH
}

// ---------------------------------------------------------------------------
extern "C" void kernel_launch(void* const* d_in, const int* in_sizes, int n_in,
                              void* d_out, int out_size)
{
    const float* x       = (const float*)d_in[0];
    const float* weights = (const float*)d_in[1];
    const float* Wq      = (const float*)d_in[2];
    const float* Wk      = (const float*)d_in[3];
    const float* Wv      = (const float*)d_in[4];
    const float* Wg      = (const float*)d_in[5];
    const float* Wo      = (const float*)d_in[6];
    const float* bo      = (const float*)d_in[7];

    float* out = (float*)d_out;
    float* nw  = out + (size_t)BATCHN * DM;

    float *qb, *bb;
    __half *xh, *xl, *wt, *ohh, *ohl;
    cudaGetSymbolAddress((void**)&qb,  g_qkv);
    cudaGetSymbolAddress((void**)&bb,  g_beta);
    cudaGetSymbolAddress((void**)&xh,  g_xh);
    cudaGetSymbolAddress((void**)&xl,  g_xl);
    cudaGetSymbolAddress((void**)&wt,  g_wt);
    cudaGetSymbolAddress((void**)&ohh, g_ohh);
    cudaGetSymbolAddress((void**)&ohl, g_ohl);
    float* kb = qb + (size_t)BATCHN * DM;
    float* vb = kb + (size_t)BATCHN * DM;

    cudaFuncSetAttribute(mm_kernel<128, 3>,
                         cudaFuncAttributeMaxDynamicSharedMemorySize, MM_SMEM_128);
    cudaFuncSetAttribute(mm_kernel<64, 4>,
                         cudaFuncAttributeMaxDynamicSharedMemorySize, MM_SMEM_64);

    const size_t MS = (size_t)DM * DM;

    // 1) transpose + fp16 the four big weight matrices
    transhalf_kernel<<<dim3(32, 32, 4), 256>>>(Wq, Wk, Wv, Wo, wt);
    // 2) fused split x + gate
    splitbeta_kernel<<<BATCHN, 256>>>(x, xh, xl, Wg, bb);
    // 3) QKV projections (fused, grid.z = 3), 64x128 tiles
    mm_kernel<128, 3><<<dim3(8, 16, 3), 256, MM_SMEM_128>>>(
        xh, xl,
        wt + 0 * MS, wt + 1 * MS, wt + 2 * MS,
        qb, kb, vb, nullptr);
    // 4) persistent fast-weight update + read (nw -> d_out, outh pre-split fp16)
    fastweight_kernel<<<(BATCHN * HEADS) / FW_ITERS, 64>>>(
        weights, qb, kb, vb, bb, nw, ohh, ohl);
    // 5) output projection + bias, 64x64 tiles (256 CTAs)
    mm_kernel<64, 4><<<dim3(16, 16, 1), 256, MM_SMEM_64>>>(
        ohh, ohl,
        wt + 3 * MS, wt + 3 * MS, wt + 3 * MS,
        out, out, out, bo);
}

// round 12
// speedup vs baseline: 1.6869x; 1.0148x over previous
#include <cuda_runtime.h>
#include <cuda_fp16.h>
#include <cstdint>
#include <math.h>

#define DM     1024
#define BATCHN 1024
#define HEADS  16
#define DK     64

// ---------------- scratch (no allocation allowed) ----------------
__device__ float g_qkv[3u * BATCHN * DM];            // q | k | v fp32
__device__ float g_beta[BATCHN * HEADS];
__device__ __half g_xh[BATCHN * DM];                 // x split hi (fp16)
__device__ __half g_xl[BATCHN * DM];                 // x split lo (fp16)
__device__ __half g_wt[4u * DM * DM];                // W^T fp16: Wq,Wk,Wv,Wo
__device__ __half g_ohh[BATCHN * DM];                // outh split hi
__device__ __half g_ohl[BATCHN * DM];                // outh split lo

__device__ __forceinline__ uint32_t smaddr(const void* p) {
    uint32_t a;
    asm("{ .reg .u64 t; cvta.to.shared.u64 t, %1; cvt.u32.u64 %0, t; }" : "=r"(a) : "l"(p));
    return a;
}
__device__ __forceinline__ void cp16(uint32_t s, const void* g) {
    asm volatile("cp.async.cg.shared.global [%0], [%1], 16;" :: "r"(s), "l"(g));
}
__device__ __forceinline__ void cp4(uint32_t s, const void* g) {
    asm volatile("cp.async.ca.shared.global [%0], [%1], 4;" :: "r"(s), "l"(g));
}

// ---------------------------------------------------------------------------
// fused: split x -> fp16 hi/lo  AND  beta = sigmoid(x @ Wg). One CTA/batch.
// ---------------------------------------------------------------------------
__global__ __launch_bounds__(256) void splitbeta_kernel(
    const float* __restrict__ x, __half* __restrict__ hi, __half* __restrict__ lo,
    const float* __restrict__ Wg, float* __restrict__ beta)
{
    __shared__ float xs[DM];
    const int b = blockIdx.x, t = threadIdx.x;
    const int idx = b * 256 + t;
    float4 v = reinterpret_cast<const float4*>(x)[idx];
    float f[4] = {v.x, v.y, v.z, v.w};
    __half h[4], l[4];
#pragma unroll
    for (int i = 0; i < 4; i++) {
        h[i] = __float2half_rn(f[i]);
        l[i] = __float2half_rn(f[i] - __half2float(h[i]));
        xs[t * 4 + i] = f[i];
    }
    __half2* h2 = reinterpret_cast<__half2*>(hi);
    __half2* l2 = reinterpret_cast<__half2*>(lo);
    h2[idx * 2 + 0] = __half2(h[0], h[1]);
    h2[idx * 2 + 1] = __half2(h[2], h[3]);
    l2[idx * 2 + 0] = __half2(l[0], l[1]);
    l2[idx * 2 + 1] = __half2(l[2], l[3]);
    __syncthreads();

    const int w = t >> 5, lane = t & 31;
    const int hh = w * 2 + (lane >> 4);        // head for this half-warp
    const int lj = lane & 15;
    float s = 0.f;
#pragma unroll 8
    for (int i = 0; i < 64; i++) {
        const int j = lj + (i << 4);
        s = fmaf(xs[j], Wg[j * HEADS + hh], s);
    }
#pragma unroll
    for (int off = 8; off; off >>= 1) s += __shfl_xor_sync(0xffffffffu, s, off);
    if (lj == 0) beta[b * HEADS + hh] = 1.f / (1.f + expf(-s));
}

// ---------------------------------------------------------------------------
// transpose + fp16: W[K][N] -> Wt[N][K] fp16. z selects matrix.
// ---------------------------------------------------------------------------
__global__ __launch_bounds__(256) void transhalf_kernel(
    const float* __restrict__ W0, const float* __restrict__ W1,
    const float* __restrict__ W2, const float* __restrict__ W3,
    __half* __restrict__ H)
{
    __shared__ float tile[32][33];
    const int z = blockIdx.z;
    const float* W = (z == 0) ? W0 : (z == 1) ? W1 : (z == 2) ? W2 : W3;
    __half* Ht = H + (size_t)z * DM * DM;
    const int tx = threadIdx.x & 31, ty = threadIdx.x >> 5;
    const int nb = blockIdx.x * 32, kb = blockIdx.y * 32;
#pragma unroll
    for (int i = 0; i < 4; i++) {
        int k = kb + ty + i * 8;
        tile[ty + i * 8][tx] = W[(size_t)k * DM + nb + tx];
    }
    __syncthreads();
#pragma unroll
    for (int i = 0; i < 4; i++) {
        int n = nb + ty + i * 8;
        Ht[(size_t)n * DM + kb + tx] = __float2half_rn(tile[tx][ty + i * 8]);
    }
}

// ---------------------------------------------------------------------------
// fp16 2-pass GEMM on mma.sync: C = Ah*Bh + Al*Bh.
// CTA tile 64xBN (BN=128 or 64), BK=32, 8 warps, 4-stage cp.async pipeline.
// ---------------------------------------------------------------------------
#define OFF_AH    0
#define OFF_AL    4096
#define OFF_BH    8192

__device__ __forceinline__ void mma_f16(float* c, const uint32_t* a, const uint32_t* b) {
    asm volatile(
        "mma.sync.aligned.m16n8k16.row.col.f32.f16.f16.f32 "
        "{%0,%1,%2,%3}, {%4,%5,%6,%7}, {%8,%9}, {%0,%1,%2,%3};"
        : "+f"(c[0]), "+f"(c[1]), "+f"(c[2]), "+f"(c[3])
        : "r"(a[0]), "r"(a[1]), "r"(a[2]), "r"(a[3]), "r"(b[0]), "r"(b[1]));
}

template<int BN>
__device__ __forceinline__ void cp_stage_t(
    uint32_t smStage, const char* aH, const char* aL, const char* bH,
    int ktBytes, int tid)
{
    {   // A: 64 rows x 64B; thread t -> row t>>2, chunk t&3
        const int r = tid >> 2, c = tid & 3;
        const int sw = (r >> 1) & 3;
        const size_t goff = ((size_t)r << 11) + (size_t)ktBytes + (c << 4);
        const uint32_t soff = r * 64 + ((c ^ sw) << 4);
        cp16(smStage + OFF_AH + soff, aH + goff);
        cp16(smStage + OFF_AL + soff, aL + goff);
    }
    if (BN == 128) {   // B: 128 rows; thread t -> row t>>1, chunks (t&1)*2,+1
        const int r = tid >> 1;
        const int sw = (r >> 1) & 3;
#pragma unroll
        for (int cc = 0; cc < 2; cc++) {
            const int c = (tid & 1) * 2 + cc;
            const size_t goff = ((size_t)r << 11) + (size_t)ktBytes + (c << 4);
            const uint32_t soff = r * 64 + ((c ^ sw) << 4);
            cp16(smStage + OFF_BH + soff, bH + goff);
        }
    } else {           // B: 64 rows; thread t -> row t>>2, chunk t&3
        const int r = tid >> 2, c = tid & 3;
        const int sw = (r >> 1) & 3;
        const size_t goff = ((size_t)r << 11) + (size_t)ktBytes + (c << 4);
        const uint32_t soff = r * 64 + ((c ^ sw) << 4);
        cp16(smStage + OFF_BH + soff, bH + goff);
    }
    asm volatile("cp.async.commit_group;");
}

template<int BN, int MINB>
__global__ __launch_bounds__(256, MINB) void mm_kernel(
    const __half* __restrict__ Ah, const __half* __restrict__ Al,
    const __half* __restrict__ Bt0, const __half* __restrict__ Bt1,
    const __half* __restrict__ Bt2,
    float* __restrict__ C0, float* __restrict__ C1, float* __restrict__ C2,
    const float* __restrict__ bias)
{
    constexpr int STAGE = 8192 + BN * 64;
    constexpr int NI = BN / 32;
    extern __shared__ char sm[];
    uint32_t smbase;
    asm("{ .reg .u64 t; cvta.to.shared.u64 t, %1; cvt.u32.u64 %0, t; }"
        : "=r"(smbase) : "l"(sm));

    const int tid = threadIdx.x;
    const int warp = tid >> 5, lane = tid & 31;
    const int g = lane >> 2, tg = lane & 3;
    const int z = blockIdx.z;
    const __half* Bt = (z == 0) ? Bt0 : (z == 1) ? Bt1 : Bt2;
    float* C = (z == 0) ? C0 : (z == 1) ? C1 : C2;

    const int rowBase = blockIdx.y * 64;
    const int colBase = blockIdx.x * BN;
    const int warpRow = (warp & 1) * 32;
    const int warpCol = (warp >> 1) * (BN / 4);

    const char* aHp = (const char*)Ah + ((size_t)rowBase << 11);
    const char* aLp = (const char*)Al + ((size_t)rowBase << 11);
    const char* bHp = (const char*)Bt + ((size_t)colBase << 11);

    const uint32_t sig = (uint32_t)(g & 6) << 3;
    const uint32_t kp[2][2] = { { (0u ^ sig),  (16u ^ sig) },
                                { (32u ^ sig), (48u ^ sig) } };
    uint32_t aBase[2], bBase[NI];
#pragma unroll
    for (int mi = 0; mi < 2; mi++)
        aBase[mi] = (uint32_t)((warpRow + mi * 16 + g) * 64 + tg * 4);
#pragma unroll
    for (int ni = 0; ni < NI; ni++)
        bBase[ni] = (uint32_t)(OFF_BH + (warpCol + ni * 8 + g) * 64 + tg * 4);

    float acc[2][NI][4];
#pragma unroll
    for (int mi = 0; mi < 2; mi++)
#pragma unroll
        for (int ni = 0; ni < NI; ni++)
#pragma unroll
            for (int e = 0; e < 4; e++) acc[mi][ni][e] = 0.f;

    cp_stage_t<BN>(smbase + 0 * STAGE, aHp, aLp, bHp, 0,   tid);
    cp_stage_t<BN>(smbase + 1 * STAGE, aHp, aLp, bHp, 64,  tid);
    cp_stage_t<BN>(smbase + 2 * STAGE, aHp, aLp, bHp, 128, tid);

    for (int it = 0; it < 32; it++) {
        if (it < 30)       asm volatile("cp.async.wait_group 2;" ::: "memory");
        else if (it == 30) asm volatile("cp.async.wait_group 1;" ::: "memory");
        else               asm volatile("cp.async.wait_group 0;" ::: "memory");
        __syncthreads();
        if (it + 3 < 32)
            cp_stage_t<BN>(smbase + ((it + 3) & 3) * STAGE, aHp, aLp, bHp,
                           (it + 3) * 64, tid);
        const uint32_t so = smbase + (it & 3) * STAGE;

#pragma unroll
        for (int ks = 0; ks < 2; ks++) {
            const uint32_t k0 = kp[ks][0], k1 = kp[ks][1];
            uint32_t ahf[2][4];
#pragma unroll
            for (int mi = 0; mi < 2; mi++) {
                const uint32_t p0 = so + aBase[mi];
                ahf[mi][0] = *(const uint32_t*)__cvta_shared_to_generic(p0 + k0);
                ahf[mi][1] = *(const uint32_t*)__cvta_shared_to_generic(p0 + k0 + 512);
                ahf[mi][2] = *(const uint32_t*)__cvta_shared_to_generic(p0 + k1);
                ahf[mi][3] = *(const uint32_t*)__cvta_shared_to_generic(p0 + k1 + 512);
            }
            uint32_t bhf[NI][2];
#pragma unroll
            for (int ni = 0; ni < NI; ni++) {
                const uint32_t p0 = so + bBase[ni];
                bhf[ni][0] = *(const uint32_t*)__cvta_shared_to_generic(p0 + k0);
                bhf[ni][1] = *(const uint32_t*)__cvta_shared_to_generic(p0 + k1);
            }
#pragma unroll
            for (int mi = 0; mi < 2; mi++)
#pragma unroll
                for (int ni = 0; ni < NI; ni++)
                    mma_f16(acc[mi][ni], ahf[mi], bhf[ni]);
            {
                uint32_t alf[2][4];
#pragma unroll
                for (int mi = 0; mi < 2; mi++) {
                    const uint32_t p0 = so + aBase[mi] + (OFF_AL - OFF_AH);
                    alf[mi][0] = *(const uint32_t*)__cvta_shared_to_generic(p0 + k0);
                    alf[mi][1] = *(const uint32_t*)__cvta_shared_to_generic(p0 + k0 + 512);
                    alf[mi][2] = *(const uint32_t*)__cvta_shared_to_generic(p0 + k1);
                    alf[mi][3] = *(const uint32_t*)__cvta_shared_to_generic(p0 + k1 + 512);
                }
#pragma unroll
                for (int mi = 0; mi < 2; mi++)
#pragma unroll
                    for (int ni = 0; ni < NI; ni++)
                        mma_f16(acc[mi][ni], alf[mi], bhf[ni]);
            }
        }
    }

    // epilogue
#pragma unroll
    for (int mi = 0; mi < 2; mi++) {
        const int row0 = rowBase + warpRow + mi * 16 + g;
#pragma unroll
        for (int ni = 0; ni < NI; ni++) {
            const int col = colBase + warpCol + ni * 8 + tg * 2;
            float b0 = 0.f, b1 = 0.f;
            if (bias) { b0 = bias[col]; b1 = bias[col + 1]; }
            float2 v0 = make_float2(acc[mi][ni][0] + b0, acc[mi][ni][1] + b1);
            float2 v1 = make_float2(acc[mi][ni][2] + b0, acc[mi][ni][3] + b1);
            *reinterpret_cast<float2*>(&C[(size_t)row0 * DM + col]) = v0;
            *reinterpret_cast<float2*>(&C[(size_t)(row0 + 8) * DM + col]) = v1;
        }
    }
}

#define MM_SMEM_128 (4 * (8192 + 128 * 64))   // 65536
#define MM_SMEM_64  (4 * (8192 + 64 * 64))    // 49152

// ---------------------------------------------------------------------------
// persistent double-buffered fast-weight kernel. One 64-thread CTA handles
// FW_ITERS consecutive (b,h); W,k,q,v,beta for step i+1 prefetched via
// cp.async while step i computes/stores. Reg-capped for 6 CTAs/SM.
// ---------------------------------------------------------------------------
#define FW_ITERS 8

__global__ __launch_bounds__(64, 6) void fastweight_kernel(
    const float* __restrict__ weights,
    const float* __restrict__ q, const float* __restrict__ k,
    const float* __restrict__ v, const float* __restrict__ beta,
    float* __restrict__ nw,
    __half* __restrict__ ohh, __half* __restrict__ ohl)
{
    __shared__ __align__(16) float Wbuf[2][DK * DK];      // 2 x 16KB
    __shared__ __align__(16) float kqv[2][3][DK];         // k | q | v
    __shared__ float betasm[2];
    __shared__ float dsh[DK];

    const int t   = threadIdx.x;
    const int bh0 = blockIdx.x * FW_ITERS;

#define FW_PREFETCH(slot, bh)                                                   \
    do {                                                                        \
        const uint32_t sW = smaddr(&Wbuf[slot][0]);                             \
        const char* Wp = (const char*)(weights + (size_t)(bh) * (DK * DK));     \
        _Pragma("unroll")                                                       \
        for (int i = 0; i < 16; i++) {                                          \
            const uint32_t off = (uint32_t)(i * 64 + t) * 16;                   \
            cp16(sW + off, Wp + off);                                           \
        }                                                                       \
        const size_t gb = (size_t)((bh) >> 4) * DM + (size_t)((bh) & 15) * DK;  \
        if (t < 16)      cp16(smaddr(&kqv[slot][0][0]) + t * 16,                \
                              (const char*)(k + gb) + t * 16);                  \
        else if (t < 32) cp16(smaddr(&kqv[slot][1][0]) + (t - 16) * 16,         \
                              (const char*)(q + gb) + (t - 16) * 16);           \
        else if (t < 48) cp16(smaddr(&kqv[slot][2][0]) + (t - 32) * 16,         \
                              (const char*)(v + gb) + (t - 32) * 16);           \
        else if (t == 48) cp4(smaddr(&betasm[slot]), beta + (bh));              \
        asm volatile("cp.async.commit_group;");                                 \
    } while (0)

    FW_PREFETCH(0, bh0);

    for (int i = 0; i < FW_ITERS; i++) {
        const int slot = i & 1;
        if (i + 1 < FW_ITERS) {
            FW_PREFETCH((i + 1) & 1, bh0 + i + 1);
            asm volatile("cp.async.wait_group 1;" ::: "memory");
        } else {
            asm volatile("cp.async.wait_group 0;" ::: "memory");
        }
        __syncthreads();

        const int bh = bh0 + i;
        const float* Wsh = Wbuf[slot];
        const float* ksh = kqv[slot][0];
        const float* qsh = kqv[slot][1];
        const float  vval  = kqv[slot][2][t];
        const float  betav = betasm[slot];
        const size_t gb = (size_t)(bh >> 4) * DM + (size_t)(bh & 15) * DK + t;

        // v_existing: row t . k (diagonal, conflict-free)
        float s = 0.f;
#pragma unroll
        for (int j = 0; j < DK; j++) {
            const int c = (j + t) & 63;
            s = fmaf(Wsh[t * DK + c], ksh[c], s);
        }
        const float dv = betav * (vval - s);
        dsh[t] = dv;
        __syncthreads();

        float s2 = 0.f, kq = 0.f;
#pragma unroll
        for (int j = 0; j < DK; j++) {
            const int c = (j + t) & 63;
            s2 = fmaf(Wsh[t * DK + c], qsh[c], s2);
            kq = fmaf(ksh[c], qsh[c], kq);
        }
        const float o = s2 + dv * kq;
        const __half oh = __float2half_rn(o);
        ohh[gb] = oh;
        ohl[gb] = __float2half_rn(o - __half2float(oh));

        float* NW = nw + (size_t)bh * (DK * DK);
        const int r0 = t >> 4, c4 = (t & 15) << 2;
        float4 k4;
        k4.x = ksh[c4 + 0]; k4.y = ksh[c4 + 1]; k4.z = ksh[c4 + 2]; k4.w = ksh[c4 + 3];
#pragma unroll 4
        for (int j = 0; j < 16; j++) {
            const int row = r0 + j * 4;
            const float d = dsh[row];
            const float4 w4 = *reinterpret_cast<const float4*>(&Wsh[row * DK + c4]);
            float4 o4;
            o4.x = w4.x + d * k4.x;
            o4.y = w4.y + d * k4.y;
            o4.z = w4.z + d * k4.z;
            o4.w = w4.w + d * k4.w;
            __stcs(reinterpret_cast<float4*>(&NW[row * DK + c4]), o4);
        }
        __syncthreads();
    }
#undef FW_PREFETCH
}

// ---------------------------------------------------------------------------
extern "C" void kernel_launch(void* const* d_in, const int* in_sizes, int n_in,
                              void* d_out, int out_size)
{
    const float* x       = (const float*)d_in[0];
    const float* weights = (const float*)d_in[1];
    const float* Wq      = (const float*)d_in[2];
    const float* Wk      = (const float*)d_in[3];
    const float* Wv      = (const float*)d_in[4];
    const float* Wg      = (const float*)d_in[5];
    const float* Wo      = (const float*)d_in[6];
    const float* bo      = (const float*)d_in[7];

    float* out = (float*)d_out;
    float* nw  = out + (size_t)BATCHN * DM;

    float *qb, *bb;
    __half *xh, *xl, *wt, *ohh, *ohl;
    cudaGetSymbolAddress((void**)&qb,  g_qkv);
    cudaGetSymbolAddress((void**)&bb,  g_beta);
    cudaGetSymbolAddress((void**)&xh,  g_xh);
    cudaGetSymbolAddress((void**)&xl,  g_xl);
    cudaGetSymbolAddress((void**)&wt,  g_wt);
    cudaGetSymbolAddress((void**)&ohh, g_ohh);
    cudaGetSymbolAddress((void**)&ohl, g_ohl);
    float* kb = qb + (size_t)BATCHN * DM;
    float* vb = kb + (size_t)BATCHN * DM;

    cudaFuncSetAttribute(mm_kernel<128, 3>,
                         cudaFuncAttributeMaxDynamicSharedMemorySize, MM_SMEM_128);
    cudaFuncSetAttribute(mm_kernel<64, 4>,
                         cudaFuncAttributeMaxDynamicSharedMemorySize, MM_SMEM_64);

    const size_t MS = (size_t)DM * DM;

    // 1) transpose + fp16 the four big weight matrices
    transhalf_kernel<<<dim3(32, 32, 4), 256>>>(Wq, Wk, Wv, Wo, wt);
    // 2) fused split x + gate
    splitbeta_kernel<<<BATCHN, 256>>>(x, xh, xl, Wg, bb);
    // 3) QKV projections (fused, grid.z = 3), 64x128 tiles
    mm_kernel<128, 3><<<dim3(8, 16, 3), 256, MM_SMEM_128>>>(
        xh, xl,
        wt + 0 * MS, wt + 1 * MS, wt + 2 * MS,
        qb, kb, vb, nullptr);
    // 4) persistent fast-weight update + read (nw -> d_out, outh pre-split fp16)
    fastweight_kernel<<<(BATCHN * HEADS) / FW_ITERS, 64>>>(
        weights, qb, kb, vb, bb, nw, ohh, ohl);
    // 5) output projection + bias, 64x64 tiles (256 CTAs)
    mm_kernel<64, 4><<<dim3(16, 16, 1), 256, MM_SMEM_64>>>(
        ohh, ohl,
        wt + 3 * MS, wt + 3 * MS, wt + 3 * MS,
        out, out, out, bo);
}

// round 13
// speedup vs baseline: 1.9051x; 1.1294x over previous
#include <cuda_runtime.h>
#include <cuda_fp16.h>
#include <cstdint>
#include <math.h>

#define DM     1024
#define BATCHN 1024
#define HEADS  16
#define DK     64

// ---------------- scratch (no allocation allowed) ----------------
__device__ float g_qkv[3u * BATCHN * DM];            // q | k | v fp32
__device__ float g_beta[BATCHN * HEADS];
__device__ __half g_xh[BATCHN * DM];                 // x fp16
__device__ __half g_wt[4u * DM * DM];                // W^T fp16: Wq,Wk,Wv,Wo
__device__ __half g_ohh[BATCHN * DM];                // outh fp16

__device__ __forceinline__ uint32_t smaddr(const void* p) {
    uint32_t a;
    asm("{ .reg .u64 t; cvta.to.shared.u64 t, %1; cvt.u32.u64 %0, t; }" : "=r"(a) : "l"(p));
    return a;
}
__device__ __forceinline__ void cp16(uint32_t s, const void* g) {
    asm volatile("cp.async.cg.shared.global [%0], [%1], 16;" :: "r"(s), "l"(g));
}
__device__ __forceinline__ void cp4(uint32_t s, const void* g) {
    asm volatile("cp.async.ca.shared.global [%0], [%1], 4;" :: "r"(s), "l"(g));
}

// ---------------------------------------------------------------------------
// fused: x -> fp16  AND  beta = sigmoid(x @ Wg). One CTA/batch.
// ---------------------------------------------------------------------------
__global__ __launch_bounds__(256) void splitbeta_kernel(
    const float* __restrict__ x, __half* __restrict__ hi,
    const float* __restrict__ Wg, float* __restrict__ beta)
{
    __shared__ float xs[DM];
    const int b = blockIdx.x, t = threadIdx.x;
    const int idx = b * 256 + t;
    float4 v = reinterpret_cast<const float4*>(x)[idx];
    float f[4] = {v.x, v.y, v.z, v.w};
    __half h[4];
#pragma unroll
    for (int i = 0; i < 4; i++) {
        h[i] = __float2half_rn(f[i]);
        xs[t * 4 + i] = f[i];
    }
    __half2* h2 = reinterpret_cast<__half2*>(hi);
    h2[idx * 2 + 0] = __half2(h[0], h[1]);
    h2[idx * 2 + 1] = __half2(h[2], h[3]);
    __syncthreads();

    const int w = t >> 5, lane = t & 31;
    const int hh = w * 2 + (lane >> 4);        // head for this half-warp
    const int lj = lane & 15;
    float s = 0.f;
#pragma unroll 8
    for (int i = 0; i < 64; i++) {
        const int j = lj + (i << 4);
        s = fmaf(xs[j], Wg[j * HEADS + hh], s);
    }
#pragma unroll
    for (int off = 8; off; off >>= 1) s += __shfl_xor_sync(0xffffffffu, s, off);
    if (lj == 0) beta[b * HEADS + hh] = 1.f / (1.f + expf(-s));
}

// ---------------------------------------------------------------------------
// transpose + fp16: W[K][N] -> Wt[N][K] fp16. z selects matrix.
// ---------------------------------------------------------------------------
__global__ __launch_bounds__(256) void transhalf_kernel(
    const float* __restrict__ W0, const float* __restrict__ W1,
    const float* __restrict__ W2, const float* __restrict__ W3,
    __half* __restrict__ H)
{
    __shared__ float tile[32][33];
    const int z = blockIdx.z;
    const float* W = (z == 0) ? W0 : (z == 1) ? W1 : (z == 2) ? W2 : W3;
    __half* Ht = H + (size_t)z * DM * DM;
    const int tx = threadIdx.x & 31, ty = threadIdx.x >> 5;
    const int nb = blockIdx.x * 32, kb = blockIdx.y * 32;
#pragma unroll
    for (int i = 0; i < 4; i++) {
        int k = kb + ty + i * 8;
        tile[ty + i * 8][tx] = W[(size_t)k * DM + nb + tx];
    }
    __syncthreads();
#pragma unroll
    for (int i = 0; i < 4; i++) {
        int n = nb + ty + i * 8;
        Ht[(size_t)n * DM + kb + tx] = __float2half_rn(tile[tx][ty + i * 8]);
    }
}

// ---------------------------------------------------------------------------
// single-pass fp16 GEMM on mma.sync: C = A*B^T (fp32 accum).
// CTA tile 64xBN (BN=128 or 64), BK=32, 8 warps, 4-stage cp.async pipeline.
// ---------------------------------------------------------------------------
#define OFF_B 4096

__device__ __forceinline__ void mma_f16(float* c, const uint32_t* a, const uint32_t* b) {
    asm volatile(
        "mma.sync.aligned.m16n8k16.row.col.f32.f16.f16.f32 "
        "{%0,%1,%2,%3}, {%4,%5,%6,%7}, {%8,%9}, {%0,%1,%2,%3};"
        : "+f"(c[0]), "+f"(c[1]), "+f"(c[2]), "+f"(c[3])
        : "r"(a[0]), "r"(a[1]), "r"(a[2]), "r"(a[3]), "r"(b[0]), "r"(b[1]));
}

template<int BN>
__device__ __forceinline__ void cp_stage_t(
    uint32_t smStage, const char* aH, const char* bH, int ktBytes, int tid)
{
    {   // A: 64 rows x 64B = 256 chunks; thread t -> row t>>2, chunk t&3
        const int r = tid >> 2, c = tid & 3;
        const int sw = (r >> 1) & 3;
        const size_t goff = ((size_t)r << 11) + (size_t)ktBytes + (c << 4);
        const uint32_t soff = r * 64 + ((c ^ sw) << 4);
        cp16(smStage + soff, aH + goff);
    }
    if (BN == 128) {   // B: 128 rows; thread t -> row t>>1, chunks (t&1)*2,+1
        const int r = tid >> 1;
        const int sw = (r >> 1) & 3;
#pragma unroll
        for (int cc = 0; cc < 2; cc++) {
            const int c = (tid & 1) * 2 + cc;
            const size_t goff = ((size_t)r << 11) + (size_t)ktBytes + (c << 4);
            const uint32_t soff = r * 64 + ((c ^ sw) << 4);
            cp16(smStage + OFF_B + soff, bH + goff);
        }
    } else {           // B: 64 rows; thread t -> row t>>2, chunk t&3
        const int r = tid >> 2, c = tid & 3;
        const int sw = (r >> 1) & 3;
        const size_t goff = ((size_t)r << 11) + (size_t)ktBytes + (c << 4);
        const uint32_t soff = r * 64 + ((c ^ sw) << 4);
        cp16(smStage + OFF_B + soff, bH + goff);
    }
    asm volatile("cp.async.commit_group;");
}

template<int BN, int MINB>
__global__ __launch_bounds__(256, MINB) void mm_kernel(
    const __half* __restrict__ Ah,
    const __half* __restrict__ Bt0, const __half* __restrict__ Bt1,
    const __half* __restrict__ Bt2,
    float* __restrict__ C0, float* __restrict__ C1, float* __restrict__ C2,
    const float* __restrict__ bias)
{
    constexpr int STAGE = 4096 + BN * 64;
    constexpr int NI = BN / 32;
    extern __shared__ char sm[];
    uint32_t smbase;
    asm("{ .reg .u64 t; cvta.to.shared.u64 t, %1; cvt.u32.u64 %0, t; }"
        : "=r"(smbase) : "l"(sm));

    const int tid = threadIdx.x;
    const int warp = tid >> 5, lane = tid & 31;
    const int g = lane >> 2, tg = lane & 3;
    const int z = blockIdx.z;
    const __half* Bt = (z == 0) ? Bt0 : (z == 1) ? Bt1 : Bt2;
    float* C = (z == 0) ? C0 : (z == 1) ? C1 : C2;

    const int rowBase = blockIdx.y * 64;
    const int colBase = blockIdx.x * BN;
    const int warpRow = (warp & 1) * 32;
    const int warpCol = (warp >> 1) * (BN / 4);

    const char* aHp = (const char*)Ah + ((size_t)rowBase << 11);
    const char* bHp = (const char*)Bt + ((size_t)colBase << 11);

    const uint32_t sig = (uint32_t)(g & 6) << 3;
    const uint32_t kp[2][2] = { { (0u ^ sig),  (16u ^ sig) },
                                { (32u ^ sig), (48u ^ sig) } };
    uint32_t aBase[2], bBase[NI];
#pragma unroll
    for (int mi = 0; mi < 2; mi++)
        aBase[mi] = (uint32_t)((warpRow + mi * 16 + g) * 64 + tg * 4);
#pragma unroll
    for (int ni = 0; ni < NI; ni++)
        bBase[ni] = (uint32_t)(OFF_B + (warpCol + ni * 8 + g) * 64 + tg * 4);

    float acc[2][NI][4];
#pragma unroll
    for (int mi = 0; mi < 2; mi++)
#pragma unroll
        for (int ni = 0; ni < NI; ni++)
#pragma unroll
            for (int e = 0; e < 4; e++) acc[mi][ni][e] = 0.f;

    cp_stage_t<BN>(smbase + 0 * STAGE, aHp, bHp, 0,   tid);
    cp_stage_t<BN>(smbase + 1 * STAGE, aHp, bHp, 64,  tid);
    cp_stage_t<BN>(smbase + 2 * STAGE, aHp, bHp, 128, tid);

    for (int it = 0; it < 32; it++) {
        if (it < 30)       asm volatile("cp.async.wait_group 2;" ::: "memory");
        else if (it == 30) asm volatile("cp.async.wait_group 1;" ::: "memory");
        else               asm volatile("cp.async.wait_group 0;" ::: "memory");
        __syncthreads();
        if (it + 3 < 32)
            cp_stage_t<BN>(smbase + ((it + 3) & 3) * STAGE, aHp, bHp,
                           (it + 3) * 64, tid);
        const uint32_t so = smbase + (it & 3) * STAGE;

#pragma unroll
        for (int ks = 0; ks < 2; ks++) {
            const uint32_t k0 = kp[ks][0], k1 = kp[ks][1];
            uint32_t ahf[2][4];
#pragma unroll
            for (int mi = 0; mi < 2; mi++) {
                const uint32_t p0 = so + aBase[mi];
                ahf[mi][0] = *(const uint32_t*)__cvta_shared_to_generic(p0 + k0);
                ahf[mi][1] = *(const uint32_t*)__cvta_shared_to_generic(p0 + k0 + 512);
                ahf[mi][2] = *(const uint32_t*)__cvta_shared_to_generic(p0 + k1);
                ahf[mi][3] = *(const uint32_t*)__cvta_shared_to_generic(p0 + k1 + 512);
            }
            uint32_t bhf[NI][2];
#pragma unroll
            for (int ni = 0; ni < NI; ni++) {
                const uint32_t p0 = so + bBase[ni];
                bhf[ni][0] = *(const uint32_t*)__cvta_shared_to_generic(p0 + k0);
                bhf[ni][1] = *(const uint32_t*)__cvta_shared_to_generic(p0 + k1);
            }
#pragma unroll
            for (int mi = 0; mi < 2; mi++)
#pragma unroll
                for (int ni = 0; ni < NI; ni++)
                    mma_f16(acc[mi][ni], ahf[mi], bhf[ni]);
        }
    }

    // epilogue
#pragma unroll
    for (int mi = 0; mi < 2; mi++) {
        const int row0 = rowBase + warpRow + mi * 16 + g;
#pragma unroll
        for (int ni = 0; ni < NI; ni++) {
            const int col = colBase + warpCol + ni * 8 + tg * 2;
            float b0 = 0.f, b1 = 0.f;
            if (bias) { b0 = bias[col]; b1 = bias[col + 1]; }
            float2 v0 = make_float2(acc[mi][ni][0] + b0, acc[mi][ni][1] + b1);
            float2 v1 = make_float2(acc[mi][ni][2] + b0, acc[mi][ni][3] + b1);
            *reinterpret_cast<float2*>(&C[(size_t)row0 * DM + col]) = v0;
            *reinterpret_cast<float2*>(&C[(size_t)(row0 + 8) * DM + col]) = v1;
        }
    }
}

#define MM_SMEM_128 (4 * (4096 + 128 * 64))   // 49152
#define MM_SMEM_64  (4 * (4096 + 64 * 64))    // 32768

// ---------------------------------------------------------------------------
// persistent double-buffered fast-weight kernel, 128 threads/CTA.
// One CTA handles FW_ITERS consecutive (b,h); next (b,h) prefetched via
// cp.async while current computes/stores. Threads 0-63 do the dot phases;
// all 128 share the cp.async fill and the NW stream-out.
// ---------------------------------------------------------------------------
#define FW_ITERS 8

__global__ __launch_bounds__(128, 6) void fastweight_kernel(
    const float* __restrict__ weights,
    const float* __restrict__ q, const float* __restrict__ k,
    const float* __restrict__ v, const float* __restrict__ beta,
    float* __restrict__ nw, __half* __restrict__ ohh)
{
    __shared__ __align__(16) float Wbuf[2][DK * DK];      // 2 x 16KB
    __shared__ __align__(16) float kqv[2][3][DK];         // k | q | v
    __shared__ float betasm[2];
    __shared__ float dsh[DK];

    const int t   = threadIdx.x;
    const int bh0 = blockIdx.x * FW_ITERS;

#define FW_PREFETCH(slot, bh)                                                   \
    do {                                                                        \
        const uint32_t sW = smaddr(&Wbuf[slot][0]);                             \
        const char* Wp = (const char*)(weights + (size_t)(bh) * (DK * DK));     \
        _Pragma("unroll")                                                       \
        for (int i = 0; i < 8; i++) {                                           \
            const uint32_t off = (uint32_t)(i * 128 + t) * 16;                  \
            cp16(sW + off, Wp + off);                                           \
        }                                                                       \
        const size_t gb = (size_t)((bh) >> 4) * DM + (size_t)((bh) & 15) * DK;  \
        if (t < 16)      cp16(smaddr(&kqv[slot][0][0]) + t * 16,                \
                              (const char*)(k + gb) + t * 16);                  \
        else if (t < 32) cp16(smaddr(&kqv[slot][1][0]) + (t - 16) * 16,         \
                              (const char*)(q + gb) + (t - 16) * 16);           \
        else if (t < 48) cp16(smaddr(&kqv[slot][2][0]) + (t - 32) * 16,         \
                              (const char*)(v + gb) + (t - 32) * 16);           \
        else if (t == 48) cp4(smaddr(&betasm[slot]), beta + (bh));              \
        asm volatile("cp.async.commit_group;");                                 \
    } while (0)

    FW_PREFETCH(0, bh0);

    for (int i = 0; i < FW_ITERS; i++) {
        const int slot = i & 1;
        if (i + 1 < FW_ITERS) {
            FW_PREFETCH((i + 1) & 1, bh0 + i + 1);
            asm volatile("cp.async.wait_group 1;" ::: "memory");
        } else {
            asm volatile("cp.async.wait_group 0;" ::: "memory");
        }
        __syncthreads();

        const int bh = bh0 + i;
        const float* Wsh = Wbuf[slot];
        const float* ksh = kqv[slot][0];
        const float* qsh = kqv[slot][1];
        const float  betav = betasm[slot];

        // phase 1 (threads 0-63): v_existing = row t . k (diagonal)
        if (t < DK) {
            const float vval = kqv[slot][2][t];
            float s = 0.f;
#pragma unroll
            for (int j = 0; j < DK; j++) {
                const int c = (j + t) & 63;
                s = fmaf(Wsh[t * DK + c], ksh[c], s);
            }
            dsh[t] = betav * (vval - s);
        }
        __syncthreads();

        // phase 2 (threads 0-63): out row t
        if (t < DK) {
            float s2 = 0.f, kq = 0.f;
#pragma unroll
            for (int j = 0; j < DK; j++) {
                const int c = (j + t) & 63;
                s2 = fmaf(Wsh[t * DK + c], qsh[c], s2);
                kq = fmaf(ksh[c], qsh[c], kq);
            }
            const float o = s2 + dsh[t] * kq;
            const size_t gb = (size_t)(bh >> 4) * DM + (size_t)(bh & 15) * DK + t;
            ohh[gb] = __float2half_rn(o);
        }

        // NW stream-out: 128 threads, thread t covers rows (t>>4)+8j, cols 4(t&15)
        float* NW = nw + (size_t)bh * (DK * DK);
        const int r0 = t >> 4, c4 = (t & 15) << 2;
        float4 k4;
        k4.x = ksh[c4 + 0]; k4.y = ksh[c4 + 1]; k4.z = ksh[c4 + 2]; k4.w = ksh[c4 + 3];
#pragma unroll 4
        for (int j = 0; j < 8; j++) {
            const int row = r0 + j * 8;
            const float d = dsh[row];
            const float4 w4 = *reinterpret_cast<const float4*>(&Wsh[row * DK + c4]);
            float4 o4;
            o4.x = w4.x + d * k4.x;
            o4.y = w4.y + d * k4.y;
            o4.z = w4.z + d * k4.z;
            o4.w = w4.w + d * k4.w;
            __stcs(reinterpret_cast<float4*>(&NW[row * DK + c4]), o4);
        }
        __syncthreads();
    }
#undef FW_PREFETCH
}

// ---------------------------------------------------------------------------
extern "C" void kernel_launch(void* const* d_in, const int* in_sizes, int n_in,
                              void* d_out, int out_size)
{
    const float* x       = (const float*)d_in[0];
    const float* weights = (const float*)d_in[1];
    const float* Wq      = (const float*)d_in[2];
    const float* Wk      = (const float*)d_in[3];
    const float* Wv      = (const float*)d_in[4];
    const float* Wg      = (const float*)d_in[5];
    const float* Wo      = (const float*)d_in[6];
    const float* bo      = (const float*)d_in[7];

    float* out = (float*)d_out;
    float* nw  = out + (size_t)BATCHN * DM;

    float *qb, *bb;
    __half *xh, *wt, *ohh;
    cudaGetSymbolAddress((void**)&qb,  g_qkv);
    cudaGetSymbolAddress((void**)&bb,  g_beta);
    cudaGetSymbolAddress((void**)&xh,  g_xh);
    cudaGetSymbolAddress((void**)&wt,  g_wt);
    cudaGetSymbolAddress((void**)&ohh, g_ohh);
    float* kb = qb + (size_t)BATCHN * DM;
    float* vb = kb + (size_t)BATCHN * DM;

    cudaFuncSetAttribute(mm_kernel<128, 3>,
                         cudaFuncAttributeMaxDynamicSharedMemorySize, MM_SMEM_128);
    cudaFuncSetAttribute(mm_kernel<64, 4>,
                         cudaFuncAttributeMaxDynamicSharedMemorySize, MM_SMEM_64);

    const size_t MS = (size_t)DM * DM;

    // 1) transpose + fp16 the four big weight matrices
    transhalf_kernel<<<dim3(32, 32, 4), 256>>>(Wq, Wk, Wv, Wo, wt);
    // 2) fused x->fp16 + gate
    splitbeta_kernel<<<BATCHN, 256>>>(x, xh, Wg, bb);
    // 3) QKV projections (fused, grid.z = 3), 64x128 tiles
    mm_kernel<128, 3><<<dim3(8, 16, 3), 256, MM_SMEM_128>>>(
        xh,
        wt + 0 * MS, wt + 1 * MS, wt + 2 * MS,
        qb, kb, vb, nullptr);
    // 4) persistent fast-weight update + read (nw -> d_out, outh fp16)
    fastweight_kernel<<<(BATCHN * HEADS) / FW_ITERS, 128>>>(
        weights, qb, kb, vb, bb, nw, ohh);
    // 5) output projection + bias, 64x64 tiles (256 CTAs)
    mm_kernel<64, 4><<<dim3(16, 16, 1), 256, MM_SMEM_64>>>(
        ohh,
        wt + 3 * MS, wt + 3 * MS, wt + 3 * MS,
        out, out, out, bo);
}